// round 15
// baseline (speedup 1.0000x reference)
#include <cuda_runtime.h>
#include <math.h>
#include <stdint.h>

#define BATCH 64
#define TLEN  4096
#define BT    (BATCH*TLEN)
#define C     192

__device__ float g_h0[(size_t)BT*C];
__device__ float g_h1[(size_t)BT*C];
__device__ float g_p[(size_t)BT*32];
__device__ float g_lad[BT];

// branchless GELU: erf via Abramowitz-Stegun 7.1.26 (|err| <= 1.5e-7)
__device__ __forceinline__ float geluf(float xv) {
    float u  = xv * 0.7071067811865475f;
    float au = fabsf(u);
    float t  = __frcp_rn(fmaf(0.3275911f, au, 1.f));
    float p  = fmaf(t, 1.061405429f, -1.453152027f);
    p = fmaf(t, p, 1.421413741f);
    p = fmaf(t, p, -0.284496736f);
    p = fmaf(t, p, 0.254829592f);
    p = p * t;
    float e   = __expf(-u*u);
    float erf = copysignf(fmaf(-p, e, 1.f), u);
    return 0.5f * xv * (1.f + erf);
}
__device__ __forceinline__ uint32_t smem_u32(const void* p) {
    uint32_t a;
    asm("{ .reg .u64 t; cvta.to.shared.u64 t, %1; cvt.u32.u64 %0, t; }" : "=r"(a) : "l"(p));
    return a;
}
__device__ __forceinline__ void cp16(uint32_t dst, const void* src) {
    asm volatile("cp.async.cg.shared.global [%0], [%1], 16;" :: "r"(dst), "l"(src));
}
#define CP_COMMIT() asm volatile("cp.async.commit_group;" ::: "memory")
#define CP_WAIT(n)  asm volatile("cp.async.wait_group %0;" :: "n"(n) : "memory")

// mma with k-remap: thread kq holds physical k = 2kq, 2kq+1 (consistent A/B)
__device__ __forceinline__ void mma_tf32(float* d, uint32_t a0, uint32_t a1,
                                         uint32_t a2, uint32_t a3,
                                         uint32_t b0, uint32_t b1) {
    asm volatile("mma.sync.aligned.m16n8k8.row.col.f32.tf32.tf32.f32 "
        "{%0,%1,%2,%3}, {%4,%5,%6,%7}, {%8,%9}, {%0,%1,%2,%3};"
        : "+f"(d[0]), "+f"(d[1]), "+f"(d[2]), "+f"(d[3])
        : "r"(a0), "r"(a1), "r"(a2), "r"(a3), "r"(b0), "r"(b1));
}

#define LY_YS_STR 200
#define LY_W_STR  40
#define LY_W_OFF  51200                 // bytes: 64*200*4
#define SMEM_FL   112640                // + 2*192*40*4

// ---------------------------------------------------------------------------
// Fused layer: 64 positions/block, 256 threads (8 warps: 4 M x 2 N)
// last=1: also computes proj (h @ Wp^T) in-kernel
// ---------------------------------------------------------------------------
__global__ __launch_bounds__(256, 2) void fused_layer_mma(
    const float* __restrict__ hin, float* __restrict__ hout,
    const float* __restrict__ W,  const float* __restrict__ bias,
    const float* __restrict__ g2, const float* __restrict__ b2,
    const float* __restrict__ sw, const float* __restrict__ sb,
    const float* __restrict__ g1, const float* __restrict__ b1,
    const float* __restrict__ mask, const float* __restrict__ x,
    const float* __restrict__ prew, const float* __restrict__ preb,
    const float* __restrict__ Wp,  const float* __restrict__ bpj,
    int d, int first, int last)
{
    extern __shared__ char smem[];
    float*    ysf = (float*)smem;                      // [64][200]
    uint32_t* ysu = (uint32_t*)smem;
    float*    Wc  = (float*)(smem + LY_W_OFF);         // [2][192][40]
    float*    ps1 = Wc + 192*LY_W_STR;                 // buf1 region (post-GEMM)
    float*    ps2 = ps1 + 128;
    float*    psP = ps1 + 256;                         // [64][33] proj partials
    uint32_t  sW  = smem_u32(Wc);
    int tid = threadIdx.x, lane = tid & 31, w = tid >> 5;
    int m0 = blockIdx.x * 64;

    auto issueW = [&](int kb) {
        #pragma unroll
        for (int i = 0; i < 6; i++) {
            int idx = tid + i*256;
            int co = idx >> 3, q = idx & 7;
            uint32_t dst = sW + (uint32_t)((kb & 1)*192*LY_W_STR + co*LY_W_STR + q*4)*4u;
            cp16(dst, W + co*192 + kb*32 + q*4);
        }
        CP_COMMIT();
    };
    issueW(0); issueW(1);

    // ---- dw + LN1 + gelu -> ysf (2-row pipeline); stash residual base ----
    for (int rp = 0; rp < 4; rp++) {
        int rowB = w*8 + rp*2;
        float v[2][6], s1[2], s2[2];
        float mC[2], mL[2], mR[2];
        bool hasL[2], hasR[2];
        const float* hrow[2];
        float* horow[2];
        float x0C[2], x0L[2], x0R[2];
        #pragma unroll
        for (int u = 0; u < 2; u++) {
            int pos = m0 + rowB + u;
            int t = pos & 4095;
            mC[u] = mask[pos];
            hasL[u] = (t >= d); hasR[u] = (t + d < TLEN);
            mL[u] = hasL[u] ? mask[pos-d] : 0.f;
            mR[u] = hasR[u] ? mask[pos+d] : 0.f;
            hrow[u]  = hin  + (size_t)pos*C;
            horow[u] = hout + (size_t)pos*C;
            x0C[u]=0.f; x0L[u]=0.f; x0R[u]=0.f;
            if (first) {
                const float* xr = x + (size_t)(pos >> 12)*2*TLEN;
                x0C[u] = xr[t];
                if (hasL[u]) x0L[u] = xr[t-d];
                if (hasR[u]) x0R[u] = xr[t+d];
            }
            s1[u]=0.f; s2[u]=0.f;
        }
        #pragma unroll
        for (int k = 0; k < 6; k++) {
            int c = lane + 32*k;
            #pragma unroll
            for (int u = 0; u < 2; u++) {
                float hC, hL = 0.f, hR = 0.f;
                if (first) {
                    float pw = prew[c], pb = preb[c];
                    hC = fmaf(pw, x0C[u], pb);
                    if (hasL[u]) hL = fmaf(pw, x0L[u], pb);
                    if (hasR[u]) hR = fmaf(pw, x0R[u], pb);
                } else {
                    hC = hrow[u][c];
                    horow[u][c] = hC;
                    if (hasL[u]) hL = hrow[u][c - d*C];
                    if (hasR[u]) hR = hrow[u][c + d*C];
                }
                float y = sb[c];
                y = fmaf(sw[c*3+1], hC*mC[u], y);
                if (hasL[u]) y = fmaf(sw[c*3+0], hL*mL[u], y);
                if (hasR[u]) y = fmaf(sw[c*3+2], hR*mR[u], y);
                v[u][k] = y; s1[u] += y; s2[u] += y*y;
            }
        }
        #pragma unroll
        for (int o=16;o;o>>=1) {
            s1[0] += __shfl_xor_sync(0xffffffffu, s1[0], o);
            s2[0] += __shfl_xor_sync(0xffffffffu, s2[0], o);
            s1[1] += __shfl_xor_sync(0xffffffffu, s1[1], o);
            s2[1] += __shfl_xor_sync(0xffffffffu, s2[1], o);
        }
        #pragma unroll
        for (int u = 0; u < 2; u++) {
            float mean = s1[u]*(1.f/192.f);
            float var  = s2[u]*(1.f/192.f) - mean*mean;
            float inv  = rsqrtf(var + 1e-5f);
            #pragma unroll
            for (int k=0;k<6;k++){
                int c = lane + 32*k;
                float uu = fmaf(g1[c], (v[u][k]-mean)*inv, b1[c]);
                ysf[(rowB+u)*LY_YS_STR + c] = geluf(uu);
            }
        }
    }

    // ---- GEMM: warp (mw, nw) -> rows mw*16..+15, cols nw*96..+95 ----
    int mw = w & 3, nw = w >> 2;
    int gr = lane >> 2, kq = lane & 3;
    float acc[12][4];
    #pragma unroll
    for (int nf=0;nf<12;nf++)
        #pragma unroll
        for (int i=0;i<4;i++) acc[nf][i] = 0.f;

    #pragma unroll 1
    for (int kb = 0; kb < 6; kb++) {
        if (kb < 5) { CP_WAIT(1); } else { CP_WAIT(0); }
        __syncthreads();
        const float* wb = Wc + (kb & 1)*192*LY_W_STR;
        #pragma unroll
        for (int k4 = 0; k4 < 4; k4++) {
            int ko = kb*32 + k4*8 + kq*2;
            uint2 aP0 = *reinterpret_cast<const uint2*>(&ysu[(mw*16 + gr    )*LY_YS_STR + ko]);
            uint2 aP1 = *reinterpret_cast<const uint2*>(&ysu[(mw*16 + gr + 8)*LY_YS_STR + ko]);
            #pragma unroll
            for (int nf = 0; nf < 12; nf++) {
                int col = nw*96 + nf*8 + gr;
                uint2 bP = *reinterpret_cast<const uint2*>(&wb[col*LY_W_STR + k4*8 + kq*2]);
                mma_tf32(acc[nf], aP0.x, aP1.x, aP0.y, aP1.y, bP.x, bP.y);
            }
        }
        __syncthreads();
        if (kb + 2 < 6) issueW(kb + 2);
        if (last && kb == 4) {
            #pragma unroll
            for (int i = 0; i < 6; i++) {
                int idx = tid + i*256;
                if (idx < 29*48) {
                    int j = idx / 48, q = idx % 48;
                    cp16(sW + (uint32_t)(j*LY_YS_STR + q*4)*4u, Wp + j*192 + q*4);
                }
            }
            CP_COMMIT();
        }
    }

    // ---- epilogue: bias, LN2, gelu -> ysf ----
    {
        float s1r0=0.f, s2r0=0.f, s1r1=0.f, s2r1=0.f;
        #pragma unroll
        for (int nf = 0; nf < 12; nf++) {
            int c0 = nw*96 + nf*8 + kq*2;
            float bv0 = bias[c0], bv1 = bias[c0+1];
            acc[nf][0] += bv0; acc[nf][1] += bv1;
            acc[nf][2] += bv0; acc[nf][3] += bv1;
            s1r0 += acc[nf][0] + acc[nf][1];
            s2r0 += acc[nf][0]*acc[nf][0] + acc[nf][1]*acc[nf][1];
            s1r1 += acc[nf][2] + acc[nf][3];
            s2r1 += acc[nf][2]*acc[nf][2] + acc[nf][3]*acc[nf][3];
        }
        #pragma unroll
        for (int o = 1; o <= 2; o <<= 1) {
            s1r0 += __shfl_xor_sync(0xffffffffu, s1r0, o);
            s2r0 += __shfl_xor_sync(0xffffffffu, s2r0, o);
            s1r1 += __shfl_xor_sync(0xffffffffu, s1r1, o);
            s2r1 += __shfl_xor_sync(0xffffffffu, s2r1, o);
        }
        int row0 = mw*16 + gr, row1 = row0 + 8;
        if (kq == 0) {
            ps1[nw*64 + row0] = s1r0; ps2[nw*64 + row0] = s2r0;
            ps1[nw*64 + row1] = s1r1; ps2[nw*64 + row1] = s2r1;
        }
        __syncthreads();
        float S10 = ps1[row0] + ps1[64 + row0];
        float S20 = ps2[row0] + ps2[64 + row0];
        float S11 = ps1[row1] + ps1[64 + row1];
        float S21 = ps2[row1] + ps2[64 + row1];
        float mean0 = S10*(1.f/192.f);
        float inv0  = rsqrtf(S20*(1.f/192.f) - mean0*mean0 + 1e-5f);
        float mean1 = S11*(1.f/192.f);
        float inv1  = rsqrtf(S21*(1.f/192.f) - mean1*mean1 + 1e-5f);
        __syncthreads();
        #pragma unroll
        for (int nf = 0; nf < 12; nf++) {
            int c0 = nw*96 + nf*8 + kq*2;
            float ga = g2[c0], gb = g2[c0+1], ba = b2[c0], bb = b2[c0+1];
            ysf[row0*LY_YS_STR + c0    ] = geluf(fmaf(ga, (acc[nf][0]-mean0)*inv0, ba));
            ysf[row0*LY_YS_STR + c0 + 1] = geluf(fmaf(gb, (acc[nf][1]-mean0)*inv0, bb));
            ysf[row1*LY_YS_STR + c0    ] = geluf(fmaf(ga, (acc[nf][2]-mean1)*inv1, ba));
            ysf[row1*LY_YS_STR + c0 + 1] = geluf(fmaf(gb, (acc[nf][3]-mean1)*inv1, bb));
        }
    }
    __syncthreads();

    // ---- residual; last: h -> ysf (for proj), else h -> hout ----
    for (int r = 0; r < 8; r++) {
        int row = w*8 + r;
        int pos = m0 + row;
        size_t rowo = (size_t)pos*C;
        float x0v = 0.f;
        if (first) x0v = x[(size_t)(pos >> 12)*2*TLEN + (pos & 4095)];
        #pragma unroll
        for (int k = 0; k < 6; k++) {
            int c = lane + 32*k;
            float base = first ? fmaf(prew[c], x0v, preb[c]) : hout[rowo + c];
            float hv = base + ysf[row*LY_YS_STR + c];
            if (last) ysf[row*LY_YS_STR + c] = hv;
            else      hout[rowo + c] = hv;
        }
    }

    // ---- fused proj (last layer): p = h @ Wp^T, M=64, N=32(29), K=192 ----
    if (last) {
        __syncthreads();
        const uint32_t* WpS = (const uint32_t*)Wc;   // [29][200]
        int mw2 = w & 3, kw2 = w >> 2;
        float pacc[4][4];
        #pragma unroll
        for (int nf=0;nf<4;nf++)
            #pragma unroll
            for (int i=0;i<4;i++) pacc[nf][i] = 0.f;
        #pragma unroll
        for (int ks = 0; ks < 12; ks++) {
            int ko = kw2*96 + ks*8 + kq*2;
            uint2 aP0 = *reinterpret_cast<const uint2*>(&ysu[(mw2*16 + gr    )*LY_YS_STR + ko]);
            uint2 aP1 = *reinterpret_cast<const uint2*>(&ysu[(mw2*16 + gr + 8)*LY_YS_STR + ko]);
            #pragma unroll
            for (int nf = 0; nf < 4; nf++) {
                uint2 bP = *reinterpret_cast<const uint2*>(&WpS[(nf*8 + gr)*LY_YS_STR + ko]);
                mma_tf32(pacc[nf], aP0.x, aP1.x, aP0.y, aP1.y, bP.x, bP.y);
            }
        }
        if (kw2 == 0) {
            #pragma unroll
            for (int nf = 0; nf < 4; nf++) {
                int j = nf*8 + kq*2;
                psP[(mw2*16 + gr    )*33 + j    ] = pacc[nf][0];
                psP[(mw2*16 + gr    )*33 + j + 1] = pacc[nf][1];
                psP[(mw2*16 + gr + 8)*33 + j    ] = pacc[nf][2];
                psP[(mw2*16 + gr + 8)*33 + j + 1] = pacc[nf][3];
            }
        }
        __syncthreads();
        if (kw2 == 1) {
            int row0 = mw2*16 + gr, row1 = row0 + 8;
            float mA = mask[m0 + row0];
            float mB = mask[m0 + row1];
            float* gpA = g_p + (size_t)(m0 + row0)*32;
            float* gpB = g_p + (size_t)(m0 + row1)*32;
            #pragma unroll
            for (int nf = 0; nf < 4; nf++) {
                int j = nf*8 + kq*2;
                #pragma unroll
                for (int e = 0; e < 2; e++) {
                    int jj = j + e;
                    if (jj < 29) {
                        float bv = bpj[jj];
                        gpA[jj] = fmaf(mA, pacc[nf][e  ] + psP[row0*33 + jj], bv) * mA;
                        gpB[jj] = fmaf(mB, pacc[nf][e+2] + psP[row1*33 + jj], bv) * mB;
                    }
                }
            }
        }
    }
}

// ---------------------------------------------------------------------------
// rational-quadratic spline (fast math)
// ---------------------------------------------------------------------------
__global__ __launch_bounds__(256) void spline_kernel(
    const float* __restrict__ x, const float* __restrict__ mask,
    float* __restrict__ out)
{
    int pos = blockIdx.x*256 + threadIdx.x;
    int b = pos >> 12, t = pos & 4095;
    float m = mask[pos];
    const float* p = g_p + (size_t)pos*32;
    const float ISCALE = 0.07216878364870323f;   // 1/sqrt(192)

    float x0v = x[(size_t)b*2*TLEN + t];
    float x1v = x[(size_t)b*2*TLEN + TLEN + t];

    float cw[11], wd[10];
    {
        float u[10]; float mx = -1e30f;
        #pragma unroll
        for (int k=0;k<10;k++){ u[k] = p[k]*ISCALE; mx = fmaxf(mx,u[k]); }
        float s=0.f; float e[10];
        #pragma unroll
        for (int k=0;k<10;k++){ e[k]=__expf(u[k]-mx); s+=e[k]; }
        float rs = __fdividef(1.f, s);
        float run=0.f; cw[0]=-5.f;
        #pragma unroll
        for (int k=0;k<10;k++){ run += 0.001f + 0.99f*e[k]*rs; cw[k+1] = 10.f*run - 5.f; }
        cw[10] = 5.f;
        #pragma unroll
        for (int k=0;k<10;k++) wd[k] = cw[k+1]-cw[k];
    }
    float ch[11], hg[10];
    {
        float u[10]; float mx = -1e30f;
        #pragma unroll
        for (int k=0;k<10;k++){ u[k] = p[10+k]*ISCALE; mx = fmaxf(mx,u[k]); }
        float s=0.f; float e[10];
        #pragma unroll
        for (int k=0;k<10;k++){ e[k]=__expf(u[k]-mx); s+=e[k]; }
        float rs = __fdividef(1.f, s);
        float run=0.f; ch[0]=-5.f;
        #pragma unroll
        for (int k=0;k<10;k++){ run += 0.001f + 0.99f*e[k]*rs; ch[k+1] = 10.f*run - 5.f; }
        ch[10] = 5.f;
        #pragma unroll
        for (int k=0;k<10;k++) hg[k] = ch[k+1]-ch[k];
    }
    float dv[11];
    dv[0] = 1.0f; dv[10] = 1.0f;
    #pragma unroll
    for (int k=0;k<9;k++){
        float q = p[20+k];
        float sp = (q > 20.f) ? q : __logf(1.f + __expf(q));
        dv[k+1] = 0.001f + sp;
    }
    float xin = fminf(fmaxf(x1v, -5.f), 5.f);
    int cnt = 0;
    #pragma unroll
    for (int k=0;k<10;k++) cnt += (xin >= cw[k]) ? 1 : 0;
    int bin = cnt-1; if (bin < 0) bin = 0; if (bin > 9) bin = 9;

    float icw=cw[bin], iw=wd[bin], ich=ch[bin], ih=hg[bin];
    float dl=dv[bin], dr=dv[bin+1];
    float riw = __fdividef(1.f, iw);
    float delta = ih*riw;
    float th  = (xin - icw)*riw;
    float t1m = th*(1.f-th);
    float num = ih*(delta*th*th + dl*t1m);
    float den = delta + (dl+dr-2.f*delta)*t1m;
    float yv  = ich + __fdividef(num, den);
    float onem = 1.f-th;
    float dnum = delta*delta*(dr*th*th + 2.f*delta*t1m + dl*onem*onem);
    float lad  = __logf(dnum) - 2.f*__logf(den);
    bool inside = (x1v >= -5.f) && (x1v <= 5.f);
    float xo   = inside ? yv  : x1v;
    float ladv = inside ? lad : 0.f;

    out[(size_t)b*2*TLEN + t]        = x0v * m;
    out[(size_t)b*2*TLEN + TLEN + t] = xo  * m;
    g_lad[pos] = ladv * m;
}

__global__ void logdet_kernel(float* __restrict__ out) {
    int b = blockIdx.x, tid = threadIdx.x;
    float s = 0.f;
    #pragma unroll
    for (int k=0;k<16;k++) s += g_lad[b*TLEN + k*256 + tid];
    __shared__ float smr[256];
    smr[tid] = s; __syncthreads();
    #pragma unroll
    for (int o=128;o;o>>=1){ if (tid<o) smr[tid]+=smr[tid+o]; __syncthreads(); }
    if (tid==0) out[b] = smr[0];
}

extern "C" void kernel_launch(void* const* d_in, const int* in_sizes, int n_in,
                              void* d_out, int out_size) {
    const float* x      = (const float*)d_in[0];
    const float* mask   = (const float*)d_in[1];
    const float* pre_w  = (const float*)d_in[2];
    const float* pre_b  = (const float*)d_in[3];
    const float* sep_w  = (const float*)d_in[4];
    const float* sep_b  = (const float*)d_in[5];
    const float* pw_w   = (const float*)d_in[6];
    const float* pw_b   = (const float*)d_in[7];
    const float* ln1_g  = (const float*)d_in[8];
    const float* ln1_b  = (const float*)d_in[9];
    const float* ln2_g  = (const float*)d_in[10];
    const float* ln2_b  = (const float*)d_in[11];
    const float* proj_w = (const float*)d_in[12];
    const float* proj_b = (const float*)d_in[13];
    float* out = (float*)d_out;

    float* hbuf[2];
    cudaGetSymbolAddress((void**)&hbuf[0], g_h0);
    cudaGetSymbolAddress((void**)&hbuf[1], g_h1);

    cudaFuncSetAttribute(fused_layer_mma,
                         cudaFuncAttributeMaxDynamicSharedMemorySize, SMEM_FL);

    int d = 1;
    for (int i = 0; i < 3; i++) {
        int first = (i == 0);
        int last  = (i == 2);
        const float* hin = hbuf[(i+1) & 1];
        float* hout      = hbuf[i & 1];
        fused_layer_mma<<<BT/64, 256, SMEM_FL>>>(
            hin, hout,
            pw_w + (size_t)i*C*C, pw_b + (size_t)i*C,
            ln2_g + (size_t)i*C, ln2_b + (size_t)i*C,
            sep_w + (size_t)i*C*3, sep_b + (size_t)i*C,
            ln1_g + (size_t)i*C, ln1_b + (size_t)i*C,
            mask, x, pre_w, pre_b,
            proj_w, proj_b, d, first, last);
        d *= 3;
    }

    spline_kernel<<<BT/256, 256>>>(x, mask, out);
    logdet_kernel<<<64, 256>>>(out + (size_t)BATCH*2*TLEN);
}

// round 16
// speedup vs baseline: 1.1518x; 1.1518x over previous
#include <cuda_runtime.h>
#include <math.h>
#include <stdint.h>

#define BATCH 64
#define TLEN  4096
#define BT    (BATCH*TLEN)
#define C     192

__device__ float g_h0[(size_t)BT*C];
__device__ float g_h1[(size_t)BT*C];
__device__ float g_p[(size_t)BT*32];
__device__ float g_lad[1024];           // per-spline-block partials

__device__ __forceinline__ float geluf(float u) {
    return 0.5f*u*(1.f + erff(u*0.7071067811865475f));
}
__device__ __forceinline__ uint32_t smem_u32(const void* p) {
    uint32_t a;
    asm("{ .reg .u64 t; cvta.to.shared.u64 t, %1; cvt.u32.u64 %0, t; }" : "=r"(a) : "l"(p));
    return a;
}
__device__ __forceinline__ void cp16(uint32_t dst, const void* src) {
    asm volatile("cp.async.cg.shared.global [%0], [%1], 16;" :: "r"(dst), "l"(src));
}
#define CP_COMMIT() asm volatile("cp.async.commit_group;" ::: "memory")
#define CP_WAIT(n)  asm volatile("cp.async.wait_group %0;" :: "n"(n) : "memory")

// mma with k-remap: thread kq holds physical k = 2kq, 2kq+1 (consistent A/B)
__device__ __forceinline__ void mma_tf32(float* d, uint32_t a0, uint32_t a1,
                                         uint32_t a2, uint32_t a3,
                                         uint32_t b0, uint32_t b1) {
    asm volatile("mma.sync.aligned.m16n8k8.row.col.f32.tf32.tf32.f32 "
        "{%0,%1,%2,%3}, {%4,%5,%6,%7}, {%8,%9}, {%0,%1,%2,%3};"
        : "+f"(d[0]), "+f"(d[1]), "+f"(d[2]), "+f"(d[3])
        : "r"(a0), "r"(a1), "r"(a2), "r"(a3), "r"(b0), "r"(b1));
}

#define LY_YS_STR 200
#define LY_W_STR  40
#define LY_W_OFF  51200                 // bytes: 64*200*4
#define SMEM_FL   112640                // + 2*192*40*4

// ---------------------------------------------------------------------------
// Fused layer: 64 positions/block, 256 threads (8 warps: 4 M x 2 N)
// last=1: also computes proj (h @ Wp^T) in-kernel
// ---------------------------------------------------------------------------
__global__ __launch_bounds__(256, 2) void fused_layer_mma(
    const float* __restrict__ hin, float* __restrict__ hout,
    const float* __restrict__ W,  const float* __restrict__ bias,
    const float* __restrict__ g2, const float* __restrict__ b2,
    const float* __restrict__ sw, const float* __restrict__ sb,
    const float* __restrict__ g1, const float* __restrict__ b1,
    const float* __restrict__ mask, const float* __restrict__ x,
    const float* __restrict__ prew, const float* __restrict__ preb,
    const float* __restrict__ Wp,  const float* __restrict__ bpj,
    int d, int first, int last)
{
    extern __shared__ char smem[];
    float*    ysf = (float*)smem;                      // [64][200]
    uint32_t* ysu = (uint32_t*)smem;
    float*    Wc  = (float*)(smem + LY_W_OFF);         // [2][192][40]
    float*    ps1 = Wc + 192*LY_W_STR;                 // buf1 region (post-GEMM)
    float*    ps2 = ps1 + 128;
    float*    psP = ps1 + 256;                         // [64][33] proj partials
    uint32_t  sW  = smem_u32(Wc);
    int tid = threadIdx.x, lane = tid & 31, w = tid >> 5;
    int m0 = blockIdx.x * 64;

    auto issueW = [&](int kb) {
        #pragma unroll
        for (int i = 0; i < 6; i++) {
            int idx = tid + i*256;
            int co = idx >> 3, q = idx & 7;
            uint32_t dst = sW + (uint32_t)((kb & 1)*192*LY_W_STR + co*LY_W_STR + q*4)*4u;
            cp16(dst, W + co*192 + kb*32 + q*4);
        }
        CP_COMMIT();
    };
    issueW(0); issueW(1);

    // ---- dw + LN1 + gelu -> ysf (2-row pipeline); stash residual base ----
    for (int rp = 0; rp < 4; rp++) {
        int rowB = w*8 + rp*2;
        float v[2][6], s1[2], s2[2];
        float mC[2], mL[2], mR[2];
        bool hasL[2], hasR[2];
        const float* hrow[2];
        float* horow[2];
        float x0C[2], x0L[2], x0R[2];
        #pragma unroll
        for (int u = 0; u < 2; u++) {
            int pos = m0 + rowB + u;
            int t = pos & 4095;
            mC[u] = mask[pos];
            hasL[u] = (t >= d); hasR[u] = (t + d < TLEN);
            mL[u] = hasL[u] ? mask[pos-d] : 0.f;
            mR[u] = hasR[u] ? mask[pos+d] : 0.f;
            hrow[u]  = hin  + (size_t)pos*C;
            horow[u] = hout + (size_t)pos*C;
            x0C[u]=0.f; x0L[u]=0.f; x0R[u]=0.f;
            if (first) {
                const float* xr = x + (size_t)(pos >> 12)*2*TLEN;
                x0C[u] = xr[t];
                if (hasL[u]) x0L[u] = xr[t-d];
                if (hasR[u]) x0R[u] = xr[t+d];
            }
            s1[u]=0.f; s2[u]=0.f;
        }
        #pragma unroll
        for (int k = 0; k < 6; k++) {
            int c = lane + 32*k;
            #pragma unroll
            for (int u = 0; u < 2; u++) {
                float hC, hL = 0.f, hR = 0.f;
                if (first) {
                    float pw = prew[c], pb = preb[c];
                    hC = fmaf(pw, x0C[u], pb);
                    if (hasL[u]) hL = fmaf(pw, x0L[u], pb);
                    if (hasR[u]) hR = fmaf(pw, x0R[u], pb);
                } else {
                    hC = hrow[u][c];
                    horow[u][c] = hC;
                    if (hasL[u]) hL = hrow[u][c - d*C];
                    if (hasR[u]) hR = hrow[u][c + d*C];
                }
                float y = sb[c];
                y = fmaf(sw[c*3+1], hC*mC[u], y);
                if (hasL[u]) y = fmaf(sw[c*3+0], hL*mL[u], y);
                if (hasR[u]) y = fmaf(sw[c*3+2], hR*mR[u], y);
                v[u][k] = y; s1[u] += y; s2[u] += y*y;
            }
        }
        #pragma unroll
        for (int o=16;o;o>>=1) {
            s1[0] += __shfl_xor_sync(0xffffffffu, s1[0], o);
            s2[0] += __shfl_xor_sync(0xffffffffu, s2[0], o);
            s1[1] += __shfl_xor_sync(0xffffffffu, s1[1], o);
            s2[1] += __shfl_xor_sync(0xffffffffu, s2[1], o);
        }
        #pragma unroll
        for (int u = 0; u < 2; u++) {
            float mean = s1[u]*(1.f/192.f);
            float var  = s2[u]*(1.f/192.f) - mean*mean;
            float inv  = rsqrtf(var + 1e-5f);
            #pragma unroll
            for (int k=0;k<6;k++){
                int c = lane + 32*k;
                float uu = fmaf(g1[c], (v[u][k]-mean)*inv, b1[c]);
                ysf[(rowB+u)*LY_YS_STR + c] = geluf(uu);
            }
        }
    }

    // ---- GEMM: warp (mw, nw) -> rows mw*16..+15, cols nw*96..+95 ----
    int mw = w & 3, nw = w >> 2;
    int gr = lane >> 2, kq = lane & 3;
    float acc[12][4];
    #pragma unroll
    for (int nf=0;nf<12;nf++)
        #pragma unroll
        for (int i=0;i<4;i++) acc[nf][i] = 0.f;

    #pragma unroll 1
    for (int kb = 0; kb < 6; kb++) {
        if (kb < 5) { CP_WAIT(1); } else { CP_WAIT(0); }
        __syncthreads();
        const float* wb = Wc + (kb & 1)*192*LY_W_STR;
        #pragma unroll
        for (int k4 = 0; k4 < 4; k4++) {
            int ko = kb*32 + k4*8 + kq*2;
            uint2 aP0 = *reinterpret_cast<const uint2*>(&ysu[(mw*16 + gr    )*LY_YS_STR + ko]);
            uint2 aP1 = *reinterpret_cast<const uint2*>(&ysu[(mw*16 + gr + 8)*LY_YS_STR + ko]);
            #pragma unroll
            for (int nf = 0; nf < 12; nf++) {
                int col = nw*96 + nf*8 + gr;
                uint2 bP = *reinterpret_cast<const uint2*>(&wb[col*LY_W_STR + k4*8 + kq*2]);
                mma_tf32(acc[nf], aP0.x, aP1.x, aP0.y, aP1.y, bP.x, bP.y);
            }
        }
        __syncthreads();
        if (kb + 2 < 6) issueW(kb + 2);
        if (last && kb == 4) {
            #pragma unroll
            for (int i = 0; i < 6; i++) {
                int idx = tid + i*256;
                if (idx < 29*48) {
                    int j = idx / 48, q = idx % 48;
                    cp16(sW + (uint32_t)(j*LY_YS_STR + q*4)*4u, Wp + j*192 + q*4);
                }
            }
            CP_COMMIT();
        }
    }

    // ---- epilogue: bias, LN2, gelu -> ysf ----
    {
        float s1r0=0.f, s2r0=0.f, s1r1=0.f, s2r1=0.f;
        #pragma unroll
        for (int nf = 0; nf < 12; nf++) {
            int c0 = nw*96 + nf*8 + kq*2;
            float bv0 = bias[c0], bv1 = bias[c0+1];
            acc[nf][0] += bv0; acc[nf][1] += bv1;
            acc[nf][2] += bv0; acc[nf][3] += bv1;
            s1r0 += acc[nf][0] + acc[nf][1];
            s2r0 += acc[nf][0]*acc[nf][0] + acc[nf][1]*acc[nf][1];
            s1r1 += acc[nf][2] + acc[nf][3];
            s2r1 += acc[nf][2]*acc[nf][2] + acc[nf][3]*acc[nf][3];
        }
        #pragma unroll
        for (int o = 1; o <= 2; o <<= 1) {
            s1r0 += __shfl_xor_sync(0xffffffffu, s1r0, o);
            s2r0 += __shfl_xor_sync(0xffffffffu, s2r0, o);
            s1r1 += __shfl_xor_sync(0xffffffffu, s1r1, o);
            s2r1 += __shfl_xor_sync(0xffffffffu, s2r1, o);
        }
        int row0 = mw*16 + gr, row1 = row0 + 8;
        if (kq == 0) {
            ps1[nw*64 + row0] = s1r0; ps2[nw*64 + row0] = s2r0;
            ps1[nw*64 + row1] = s1r1; ps2[nw*64 + row1] = s2r1;
        }
        __syncthreads();
        float S10 = ps1[row0] + ps1[64 + row0];
        float S20 = ps2[row0] + ps2[64 + row0];
        float S11 = ps1[row1] + ps1[64 + row1];
        float S21 = ps2[row1] + ps2[64 + row1];
        float mean0 = S10*(1.f/192.f);
        float inv0  = rsqrtf(S20*(1.f/192.f) - mean0*mean0 + 1e-5f);
        float mean1 = S11*(1.f/192.f);
        float inv1  = rsqrtf(S21*(1.f/192.f) - mean1*mean1 + 1e-5f);
        __syncthreads();
        #pragma unroll
        for (int nf = 0; nf < 12; nf++) {
            int c0 = nw*96 + nf*8 + kq*2;
            float ga = g2[c0], gb = g2[c0+1], ba = b2[c0], bb = b2[c0+1];
            ysf[row0*LY_YS_STR + c0    ] = geluf(fmaf(ga, (acc[nf][0]-mean0)*inv0, ba));
            ysf[row0*LY_YS_STR + c0 + 1] = geluf(fmaf(gb, (acc[nf][1]-mean0)*inv0, bb));
            ysf[row1*LY_YS_STR + c0    ] = geluf(fmaf(ga, (acc[nf][2]-mean1)*inv1, ba));
            ysf[row1*LY_YS_STR + c0 + 1] = geluf(fmaf(gb, (acc[nf][3]-mean1)*inv1, bb));
        }
    }
    __syncthreads();

    // ---- residual; last: h -> ysf (for proj), else h -> hout ----
    for (int r = 0; r < 8; r++) {
        int row = w*8 + r;
        int pos = m0 + row;
        size_t rowo = (size_t)pos*C;
        float x0v = 0.f;
        if (first) x0v = x[(size_t)(pos >> 12)*2*TLEN + (pos & 4095)];
        #pragma unroll
        for (int k = 0; k < 6; k++) {
            int c = lane + 32*k;
            float base = first ? fmaf(prew[c], x0v, preb[c]) : hout[rowo + c];
            float hv = base + ysf[row*LY_YS_STR + c];
            if (last) ysf[row*LY_YS_STR + c] = hv;
            else      hout[rowo + c] = hv;
        }
    }

    // ---- fused proj (last layer): p = h @ Wp^T, M=64, N=32(29), K=192 ----
    if (last) {
        __syncthreads();
        const uint32_t* WpS = (const uint32_t*)Wc;   // [29][200]
        int mw2 = w & 3, kw2 = w >> 2;
        float pacc[4][4];
        #pragma unroll
        for (int nf=0;nf<4;nf++)
            #pragma unroll
            for (int i=0;i<4;i++) pacc[nf][i] = 0.f;
        #pragma unroll
        for (int ks = 0; ks < 12; ks++) {
            int ko = kw2*96 + ks*8 + kq*2;
            uint2 aP0 = *reinterpret_cast<const uint2*>(&ysu[(mw2*16 + gr    )*LY_YS_STR + ko]);
            uint2 aP1 = *reinterpret_cast<const uint2*>(&ysu[(mw2*16 + gr + 8)*LY_YS_STR + ko]);
            #pragma unroll
            for (int nf = 0; nf < 4; nf++) {
                uint2 bP = *reinterpret_cast<const uint2*>(&WpS[(nf*8 + gr)*LY_YS_STR + ko]);
                mma_tf32(pacc[nf], aP0.x, aP1.x, aP0.y, aP1.y, bP.x, bP.y);
            }
        }
        if (kw2 == 0) {
            #pragma unroll
            for (int nf = 0; nf < 4; nf++) {
                int j = nf*8 + kq*2;
                psP[(mw2*16 + gr    )*33 + j    ] = pacc[nf][0];
                psP[(mw2*16 + gr    )*33 + j + 1] = pacc[nf][1];
                psP[(mw2*16 + gr + 8)*33 + j    ] = pacc[nf][2];
                psP[(mw2*16 + gr + 8)*33 + j + 1] = pacc[nf][3];
            }
        }
        __syncthreads();
        if (kw2 == 1) {
            int row0 = mw2*16 + gr, row1 = row0 + 8;
            float mA = mask[m0 + row0];
            float mB = mask[m0 + row1];
            float* gpA = g_p + (size_t)(m0 + row0)*32;
            float* gpB = g_p + (size_t)(m0 + row1)*32;
            #pragma unroll
            for (int nf = 0; nf < 4; nf++) {
                int j = nf*8 + kq*2;
                #pragma unroll
                for (int e = 0; e < 2; e++) {
                    int jj = j + e;
                    if (jj < 29) {
                        float bv = bpj[jj];
                        gpA[jj] = fmaf(mA, pacc[nf][e  ] + psP[row0*33 + jj], bv) * mA;
                        gpB[jj] = fmaf(mB, pacc[nf][e+2] + psP[row1*33 + jj], bv) * mB;
                    }
                }
            }
        }
    }
}

// ---------------------------------------------------------------------------
// rational-quadratic spline (fast math) + in-block deterministic lad reduce
// ---------------------------------------------------------------------------
__global__ __launch_bounds__(256) void spline_kernel(
    const float* __restrict__ x, const float* __restrict__ mask,
    float* __restrict__ out)
{
    int pos = blockIdx.x*256 + threadIdx.x;
    int b = pos >> 12, t = pos & 4095;
    float m = mask[pos];
    const float* p = g_p + (size_t)pos*32;
    const float ISCALE = 0.07216878364870323f;   // 1/sqrt(192)

    float x0v = x[(size_t)b*2*TLEN + t];
    float x1v = x[(size_t)b*2*TLEN + TLEN + t];

    float cw[11], wd[10];
    {
        float u[10]; float mx = -1e30f;
        #pragma unroll
        for (int k=0;k<10;k++){ u[k] = p[k]*ISCALE; mx = fmaxf(mx,u[k]); }
        float s=0.f; float e[10];
        #pragma unroll
        for (int k=0;k<10;k++){ e[k]=__expf(u[k]-mx); s+=e[k]; }
        float rs = __fdividef(1.f, s);
        float run=0.f; cw[0]=-5.f;
        #pragma unroll
        for (int k=0;k<10;k++){ run += 0.001f + 0.99f*e[k]*rs; cw[k+1] = 10.f*run - 5.f; }
        cw[10] = 5.f;
        #pragma unroll
        for (int k=0;k<10;k++) wd[k] = cw[k+1]-cw[k];
    }
    float ch[11], hg[10];
    {
        float u[10]; float mx = -1e30f;
        #pragma unroll
        for (int k=0;k<10;k++){ u[k] = p[10+k]*ISCALE; mx = fmaxf(mx,u[k]); }
        float s=0.f; float e[10];
        #pragma unroll
        for (int k=0;k<10;k++){ e[k]=__expf(u[k]-mx); s+=e[k]; }
        float rs = __fdividef(1.f, s);
        float run=0.f; ch[0]=-5.f;
        #pragma unroll
        for (int k=0;k<10;k++){ run += 0.001f + 0.99f*e[k]*rs; ch[k+1] = 10.f*run - 5.f; }
        ch[10] = 5.f;
        #pragma unroll
        for (int k=0;k<10;k++) hg[k] = ch[k+1]-ch[k];
    }
    float dv[11];
    dv[0] = 1.0f; dv[10] = 1.0f;
    #pragma unroll
    for (int k=0;k<9;k++){
        float q = p[20+k];
        float sp = (q > 20.f) ? q : __logf(1.f + __expf(q));
        dv[k+1] = 0.001f + sp;
    }
    float xin = fminf(fmaxf(x1v, -5.f), 5.f);
    int cnt = 0;
    #pragma unroll
    for (int k=0;k<10;k++) cnt += (xin >= cw[k]) ? 1 : 0;
    int bin = cnt-1; if (bin < 0) bin = 0; if (bin > 9) bin = 9;

    float icw=cw[bin], iw=wd[bin], ich=ch[bin], ih=hg[bin];
    float dl=dv[bin], dr=dv[bin+1];
    float riw = __fdividef(1.f, iw);
    float delta = ih*riw;
    float th  = (xin - icw)*riw;
    float t1m = th*(1.f-th);
    float num = ih*(delta*th*th + dl*t1m);
    float den = delta + (dl+dr-2.f*delta)*t1m;
    float yv  = ich + __fdividef(num, den);
    float onem = 1.f-th;
    float dnum = delta*delta*(dr*th*th + 2.f*delta*t1m + dl*onem*onem);
    float lad  = __logf(dnum) - 2.f*__logf(den);
    bool inside = (x1v >= -5.f) && (x1v <= 5.f);
    float xo   = inside ? yv  : x1v;
    float ladv = inside ? lad : 0.f;

    out[(size_t)b*2*TLEN + t]        = x0v * m;
    out[(size_t)b*2*TLEN + TLEN + t] = xo  * m;

    // deterministic in-block reduction of lad*m -> one partial per block
    __shared__ float smr[256];
    smr[threadIdx.x] = ladv * m;
    __syncthreads();
    #pragma unroll
    for (int o=128;o;o>>=1){
        if (threadIdx.x < o) smr[threadIdx.x] += smr[threadIdx.x + o];
        __syncthreads();
    }
    if (threadIdx.x == 0) g_lad[blockIdx.x] = smr[0];
}

// 16 partials per batch element, fixed order
__global__ void logdet_kernel(float* __restrict__ out) {
    int b = threadIdx.x;   // 64 threads
    float s = 0.f;
    #pragma unroll
    for (int k=0;k<16;k++) s += g_lad[b*16 + k];
    out[b] = s;
}

extern "C" void kernel_launch(void* const* d_in, const int* in_sizes, int n_in,
                              void* d_out, int out_size) {
    const float* x      = (const float*)d_in[0];
    const float* mask   = (const float*)d_in[1];
    const float* pre_w  = (const float*)d_in[2];
    const float* pre_b  = (const float*)d_in[3];
    const float* sep_w  = (const float*)d_in[4];
    const float* sep_b  = (const float*)d_in[5];
    const float* pw_w   = (const float*)d_in[6];
    const float* pw_b   = (const float*)d_in[7];
    const float* ln1_g  = (const float*)d_in[8];
    const float* ln1_b  = (const float*)d_in[9];
    const float* ln2_g  = (const float*)d_in[10];
    const float* ln2_b  = (const float*)d_in[11];
    const float* proj_w = (const float*)d_in[12];
    const float* proj_b = (const float*)d_in[13];
    float* out = (float*)d_out;

    float* hbuf[2];
    cudaGetSymbolAddress((void**)&hbuf[0], g_h0);
    cudaGetSymbolAddress((void**)&hbuf[1], g_h1);

    cudaFuncSetAttribute(fused_layer_mma,
                         cudaFuncAttributeMaxDynamicSharedMemorySize, SMEM_FL);

    int d = 1;
    for (int i = 0; i < 3; i++) {
        int first = (i == 0);
        int last  = (i == 2);
        const float* hin = hbuf[(i+1) & 1];
        float* hout      = hbuf[i & 1];
        fused_layer_mma<<<BT/64, 256, SMEM_FL>>>(
            hin, hout,
            pw_w + (size_t)i*C*C, pw_b + (size_t)i*C,
            ln2_g + (size_t)i*C, ln2_b + (size_t)i*C,
            sep_w + (size_t)i*C*3, sep_b + (size_t)i*C,
            ln1_g + (size_t)i*C, ln1_b + (size_t)i*C,
            mask, x, pre_w, pre_b,
            proj_w, proj_b, d, first, last);
        d *= 3;
    }

    spline_kernel<<<BT/256, 256>>>(x, mask, out);
    logdet_kernel<<<1, 64>>>(out + (size_t)BATCH*2*TLEN);
}

// round 17
// speedup vs baseline: 1.1565x; 1.0041x over previous
#include <cuda_runtime.h>
#include <math.h>
#include <stdint.h>

#define BATCH 64
#define TLEN  4096
#define BT    (BATCH*TLEN)
#define C     192

__device__ float g_h0[(size_t)BT*C];
__device__ float g_h1[(size_t)BT*C];
__device__ float g_p[(size_t)BT*32];
__device__ float g_lad[BT];

__device__ __forceinline__ float geluf(float u) {
    return 0.5f*u*(1.f + erff(u*0.7071067811865475f));
}
__device__ __forceinline__ uint32_t smem_u32(const void* p) {
    uint32_t a;
    asm("{ .reg .u64 t; cvta.to.shared.u64 t, %1; cvt.u32.u64 %0, t; }" : "=r"(a) : "l"(p));
    return a;
}
__device__ __forceinline__ void cp16(uint32_t dst, const void* src) {
    asm volatile("cp.async.cg.shared.global [%0], [%1], 16;" :: "r"(dst), "l"(src));
}
#define CP_COMMIT() asm volatile("cp.async.commit_group;" ::: "memory")
#define CP_WAIT(n)  asm volatile("cp.async.wait_group %0;" :: "n"(n) : "memory")

// mma with k-remap: thread kq holds physical k = 2kq, 2kq+1 (consistent A/B)
__device__ __forceinline__ void mma_tf32(float* d, uint32_t a0, uint32_t a1,
                                         uint32_t a2, uint32_t a3,
                                         uint32_t b0, uint32_t b1) {
    asm volatile("mma.sync.aligned.m16n8k8.row.col.f32.tf32.tf32.f32 "
        "{%0,%1,%2,%3}, {%4,%5,%6,%7}, {%8,%9}, {%0,%1,%2,%3};"
        : "+f"(d[0]), "+f"(d[1]), "+f"(d[2]), "+f"(d[3])
        : "r"(a0), "r"(a1), "r"(a2), "r"(a3), "r"(b0), "r"(b1));
}

#define LY_YS_STR 200
#define LY_W_STR  40
#define LY_W_OFF  51200                 // bytes: 64*200*4
#define SMEM_FL   112640                // + 2*192*40*4

// tiny deterministic kernel to shift the ncu -s window onto the layer kernel
__global__ void prof_shift_kernel() {
    if (threadIdx.x == 0 && blockIdx.x == 0) g_lad[0] = 0.f;
}

// ---------------------------------------------------------------------------
// Fused layer: 64 positions/block, 256 threads (8 warps: 4 M x 2 N)
// last=1: also computes proj (h @ Wp^T) in-kernel
// ---------------------------------------------------------------------------
__global__ __launch_bounds__(256, 2) void fused_layer_mma(
    const float* __restrict__ hin, float* __restrict__ hout,
    const float* __restrict__ W,  const float* __restrict__ bias,
    const float* __restrict__ g2, const float* __restrict__ b2,
    const float* __restrict__ sw, const float* __restrict__ sb,
    const float* __restrict__ g1, const float* __restrict__ b1,
    const float* __restrict__ mask, const float* __restrict__ x,
    const float* __restrict__ prew, const float* __restrict__ preb,
    const float* __restrict__ Wp,  const float* __restrict__ bpj,
    int d, int first, int last)
{
    extern __shared__ char smem[];
    float*    ysf = (float*)smem;                      // [64][200]
    uint32_t* ysu = (uint32_t*)smem;
    float*    Wc  = (float*)(smem + LY_W_OFF);         // [2][192][40]
    float*    ps1 = Wc + 192*LY_W_STR;                 // buf1 region (post-GEMM)
    float*    ps2 = ps1 + 128;
    float*    psP = ps1 + 256;                         // [64][33] proj partials
    uint32_t  sW  = smem_u32(Wc);
    int tid = threadIdx.x, lane = tid & 31, w = tid >> 5;
    int m0 = blockIdx.x * 64;

    auto issueW = [&](int kb) {
        #pragma unroll
        for (int i = 0; i < 6; i++) {
            int idx = tid + i*256;
            int co = idx >> 3, q = idx & 7;
            uint32_t dst = sW + (uint32_t)((kb & 1)*192*LY_W_STR + co*LY_W_STR + q*4)*4u;
            cp16(dst, W + co*192 + kb*32 + q*4);
        }
        CP_COMMIT();
    };
    issueW(0); issueW(1);

    // ---- dw + LN1 + gelu -> ysf (2-row pipeline); stash residual base ----
    for (int rp = 0; rp < 4; rp++) {
        int rowB = w*8 + rp*2;
        float v[2][6], s1[2], s2[2];
        float mC[2], mL[2], mR[2];
        bool hasL[2], hasR[2];
        const float* hrow[2];
        float* horow[2];
        float x0C[2], x0L[2], x0R[2];
        #pragma unroll
        for (int u = 0; u < 2; u++) {
            int pos = m0 + rowB + u;
            int t = pos & 4095;
            mC[u] = mask[pos];
            hasL[u] = (t >= d); hasR[u] = (t + d < TLEN);
            mL[u] = hasL[u] ? mask[pos-d] : 0.f;
            mR[u] = hasR[u] ? mask[pos+d] : 0.f;
            hrow[u]  = hin  + (size_t)pos*C;
            horow[u] = hout + (size_t)pos*C;
            x0C[u]=0.f; x0L[u]=0.f; x0R[u]=0.f;
            if (first) {
                const float* xr = x + (size_t)(pos >> 12)*2*TLEN;
                x0C[u] = xr[t];
                if (hasL[u]) x0L[u] = xr[t-d];
                if (hasR[u]) x0R[u] = xr[t+d];
            }
            s1[u]=0.f; s2[u]=0.f;
        }
        #pragma unroll
        for (int k = 0; k < 6; k++) {
            int c = lane + 32*k;
            #pragma unroll
            for (int u = 0; u < 2; u++) {
                float hC, hL = 0.f, hR = 0.f;
                if (first) {
                    float pw = prew[c], pb = preb[c];
                    hC = fmaf(pw, x0C[u], pb);
                    if (hasL[u]) hL = fmaf(pw, x0L[u], pb);
                    if (hasR[u]) hR = fmaf(pw, x0R[u], pb);
                } else {
                    hC = hrow[u][c];
                    horow[u][c] = hC;
                    if (hasL[u]) hL = hrow[u][c - d*C];
                    if (hasR[u]) hR = hrow[u][c + d*C];
                }
                float y = sb[c];
                y = fmaf(sw[c*3+1], hC*mC[u], y);
                if (hasL[u]) y = fmaf(sw[c*3+0], hL*mL[u], y);
                if (hasR[u]) y = fmaf(sw[c*3+2], hR*mR[u], y);
                v[u][k] = y; s1[u] += y; s2[u] += y*y;
            }
        }
        #pragma unroll
        for (int o=16;o;o>>=1) {
            s1[0] += __shfl_xor_sync(0xffffffffu, s1[0], o);
            s2[0] += __shfl_xor_sync(0xffffffffu, s2[0], o);
            s1[1] += __shfl_xor_sync(0xffffffffu, s1[1], o);
            s2[1] += __shfl_xor_sync(0xffffffffu, s2[1], o);
        }
        #pragma unroll
        for (int u = 0; u < 2; u++) {
            float mean = s1[u]*(1.f/192.f);
            float var  = s2[u]*(1.f/192.f) - mean*mean;
            float inv  = rsqrtf(var + 1e-5f);
            #pragma unroll
            for (int k=0;k<6;k++){
                int c = lane + 32*k;
                float uu = fmaf(g1[c], (v[u][k]-mean)*inv, b1[c]);
                ysf[(rowB+u)*LY_YS_STR + c] = geluf(uu);
            }
        }
    }

    // ---- GEMM: warp (mw, nw) -> rows mw*16..+15, cols nw*96..+95 ----
    int mw = w & 3, nw = w >> 2;
    int gr = lane >> 2, kq = lane & 3;
    float acc[12][4];
    #pragma unroll
    for (int nf=0;nf<12;nf++)
        #pragma unroll
        for (int i=0;i<4;i++) acc[nf][i] = 0.f;

    #pragma unroll 1
    for (int kb = 0; kb < 6; kb++) {
        if (kb < 5) { CP_WAIT(1); } else { CP_WAIT(0); }
        __syncthreads();
        const float* wb = Wc + (kb & 1)*192*LY_W_STR;
        #pragma unroll
        for (int k4 = 0; k4 < 4; k4++) {
            int ko = kb*32 + k4*8 + kq*2;
            uint2 aP0 = *reinterpret_cast<const uint2*>(&ysu[(mw*16 + gr    )*LY_YS_STR + ko]);
            uint2 aP1 = *reinterpret_cast<const uint2*>(&ysu[(mw*16 + gr + 8)*LY_YS_STR + ko]);
            #pragma unroll
            for (int nf = 0; nf < 12; nf++) {
                int col = nw*96 + nf*8 + gr;
                uint2 bP = *reinterpret_cast<const uint2*>(&wb[col*LY_W_STR + k4*8 + kq*2]);
                mma_tf32(acc[nf], aP0.x, aP1.x, aP0.y, aP1.y, bP.x, bP.y);
            }
        }
        __syncthreads();
        if (kb + 2 < 6) issueW(kb + 2);
        if (last && kb == 4) {
            #pragma unroll
            for (int i = 0; i < 6; i++) {
                int idx = tid + i*256;
                if (idx < 29*48) {
                    int j = idx / 48, q = idx % 48;
                    cp16(sW + (uint32_t)(j*LY_YS_STR + q*4)*4u, Wp + j*192 + q*4);
                }
            }
            CP_COMMIT();
        }
    }

    // ---- epilogue: bias, LN2, gelu -> ysf ----
    {
        float s1r0=0.f, s2r0=0.f, s1r1=0.f, s2r1=0.f;
        #pragma unroll
        for (int nf = 0; nf < 12; nf++) {
            int c0 = nw*96 + nf*8 + kq*2;
            float bv0 = bias[c0], bv1 = bias[c0+1];
            acc[nf][0] += bv0; acc[nf][1] += bv1;
            acc[nf][2] += bv0; acc[nf][3] += bv1;
            s1r0 += acc[nf][0] + acc[nf][1];
            s2r0 += acc[nf][0]*acc[nf][0] + acc[nf][1]*acc[nf][1];
            s1r1 += acc[nf][2] + acc[nf][3];
            s2r1 += acc[nf][2]*acc[nf][2] + acc[nf][3]*acc[nf][3];
        }
        #pragma unroll
        for (int o = 1; o <= 2; o <<= 1) {
            s1r0 += __shfl_xor_sync(0xffffffffu, s1r0, o);
            s2r0 += __shfl_xor_sync(0xffffffffu, s2r0, o);
            s1r1 += __shfl_xor_sync(0xffffffffu, s1r1, o);
            s2r1 += __shfl_xor_sync(0xffffffffu, s2r1, o);
        }
        int row0 = mw*16 + gr, row1 = row0 + 8;
        if (kq == 0) {
            ps1[nw*64 + row0] = s1r0; ps2[nw*64 + row0] = s2r0;
            ps1[nw*64 + row1] = s1r1; ps2[nw*64 + row1] = s2r1;
        }
        __syncthreads();
        float S10 = ps1[row0] + ps1[64 + row0];
        float S20 = ps2[row0] + ps2[64 + row0];
        float S11 = ps1[row1] + ps1[64 + row1];
        float S21 = ps2[row1] + ps2[64 + row1];
        float mean0 = S10*(1.f/192.f);
        float inv0  = rsqrtf(S20*(1.f/192.f) - mean0*mean0 + 1e-5f);
        float mean1 = S11*(1.f/192.f);
        float inv1  = rsqrtf(S21*(1.f/192.f) - mean1*mean1 + 1e-5f);
        __syncthreads();
        #pragma unroll
        for (int nf = 0; nf < 12; nf++) {
            int c0 = nw*96 + nf*8 + kq*2;
            float ga = g2[c0], gb = g2[c0+1], ba = b2[c0], bb = b2[c0+1];
            ysf[row0*LY_YS_STR + c0    ] = geluf(fmaf(ga, (acc[nf][0]-mean0)*inv0, ba));
            ysf[row0*LY_YS_STR + c0 + 1] = geluf(fmaf(gb, (acc[nf][1]-mean0)*inv0, bb));
            ysf[row1*LY_YS_STR + c0    ] = geluf(fmaf(ga, (acc[nf][2]-mean1)*inv1, ba));
            ysf[row1*LY_YS_STR + c0 + 1] = geluf(fmaf(gb, (acc[nf][3]-mean1)*inv1, bb));
        }
    }
    __syncthreads();

    // ---- residual; last: h -> ysf (for proj), else h -> hout ----
    for (int r = 0; r < 8; r++) {
        int row = w*8 + r;
        int pos = m0 + row;
        size_t rowo = (size_t)pos*C;
        float x0v = 0.f;
        if (first) x0v = x[(size_t)(pos >> 12)*2*TLEN + (pos & 4095)];
        #pragma unroll
        for (int k = 0; k < 6; k++) {
            int c = lane + 32*k;
            float base = first ? fmaf(prew[c], x0v, preb[c]) : hout[rowo + c];
            float hv = base + ysf[row*LY_YS_STR + c];
            if (last) ysf[row*LY_YS_STR + c] = hv;
            else      hout[rowo + c] = hv;
        }
    }

    // ---- fused proj (last layer): p = h @ Wp^T, M=64, N=32(29), K=192 ----
    if (last) {
        __syncthreads();
        const uint32_t* WpS = (const uint32_t*)Wc;   // [29][200]
        int mw2 = w & 3, kw2 = w >> 2;
        float pacc[4][4];
        #pragma unroll
        for (int nf=0;nf<4;nf++)
            #pragma unroll
            for (int i=0;i<4;i++) pacc[nf][i] = 0.f;
        #pragma unroll
        for (int ks = 0; ks < 12; ks++) {
            int ko = kw2*96 + ks*8 + kq*2;
            uint2 aP0 = *reinterpret_cast<const uint2*>(&ysu[(mw2*16 + gr    )*LY_YS_STR + ko]);
            uint2 aP1 = *reinterpret_cast<const uint2*>(&ysu[(mw2*16 + gr + 8)*LY_YS_STR + ko]);
            #pragma unroll
            for (int nf = 0; nf < 4; nf++) {
                uint2 bP = *reinterpret_cast<const uint2*>(&WpS[(nf*8 + gr)*LY_YS_STR + ko]);
                mma_tf32(pacc[nf], aP0.x, aP1.x, aP0.y, aP1.y, bP.x, bP.y);
            }
        }
        if (kw2 == 0) {
            #pragma unroll
            for (int nf = 0; nf < 4; nf++) {
                int j = nf*8 + kq*2;
                psP[(mw2*16 + gr    )*33 + j    ] = pacc[nf][0];
                psP[(mw2*16 + gr    )*33 + j + 1] = pacc[nf][1];
                psP[(mw2*16 + gr + 8)*33 + j    ] = pacc[nf][2];
                psP[(mw2*16 + gr + 8)*33 + j + 1] = pacc[nf][3];
            }
        }
        __syncthreads();
        if (kw2 == 1) {
            int row0 = mw2*16 + gr, row1 = row0 + 8;
            float mA = mask[m0 + row0];
            float mB = mask[m0 + row1];
            float* gpA = g_p + (size_t)(m0 + row0)*32;
            float* gpB = g_p + (size_t)(m0 + row1)*32;
            #pragma unroll
            for (int nf = 0; nf < 4; nf++) {
                int j = nf*8 + kq*2;
                #pragma unroll
                for (int e = 0; e < 2; e++) {
                    int jj = j + e;
                    if (jj < 29) {
                        float bv = bpj[jj];
                        gpA[jj] = fmaf(mA, pacc[nf][e  ] + psP[row0*33 + jj], bv) * mA;
                        gpB[jj] = fmaf(mB, pacc[nf][e+2] + psP[row1*33 + jj], bv) * mB;
                    }
                }
            }
        }
    }
}

// ---------------------------------------------------------------------------
// rational-quadratic spline (fast math)
// ---------------------------------------------------------------------------
__global__ __launch_bounds__(256) void spline_kernel(
    const float* __restrict__ x, const float* __restrict__ mask,
    float* __restrict__ out)
{
    int pos = blockIdx.x*256 + threadIdx.x;
    int b = pos >> 12, t = pos & 4095;
    float m = mask[pos];
    const float* p = g_p + (size_t)pos*32;
    const float ISCALE = 0.07216878364870323f;   // 1/sqrt(192)

    float x0v = x[(size_t)b*2*TLEN + t];
    float x1v = x[(size_t)b*2*TLEN + TLEN + t];

    float cw[11], wd[10];
    {
        float u[10]; float mx = -1e30f;
        #pragma unroll
        for (int k=0;k<10;k++){ u[k] = p[k]*ISCALE; mx = fmaxf(mx,u[k]); }
        float s=0.f; float e[10];
        #pragma unroll
        for (int k=0;k<10;k++){ e[k]=__expf(u[k]-mx); s+=e[k]; }
        float rs = __fdividef(1.f, s);
        float run=0.f; cw[0]=-5.f;
        #pragma unroll
        for (int k=0;k<10;k++){ run += 0.001f + 0.99f*e[k]*rs; cw[k+1] = 10.f*run - 5.f; }
        cw[10] = 5.f;
        #pragma unroll
        for (int k=0;k<10;k++) wd[k] = cw[k+1]-cw[k];
    }
    float ch[11], hg[10];
    {
        float u[10]; float mx = -1e30f;
        #pragma unroll
        for (int k=0;k<10;k++){ u[k] = p[10+k]*ISCALE; mx = fmaxf(mx,u[k]); }
        float s=0.f; float e[10];
        #pragma unroll
        for (int k=0;k<10;k++){ e[k]=__expf(u[k]-mx); s+=e[k]; }
        float rs = __fdividef(1.f, s);
        float run=0.f; ch[0]=-5.f;
        #pragma unroll
        for (int k=0;k<10;k++){ run += 0.001f + 0.99f*e[k]*rs; ch[k+1] = 10.f*run - 5.f; }
        ch[10] = 5.f;
        #pragma unroll
        for (int k=0;k<10;k++) hg[k] = ch[k+1]-ch[k];
    }
    float dv[11];
    dv[0] = 1.0f; dv[10] = 1.0f;
    #pragma unroll
    for (int k=0;k<9;k++){
        float q = p[20+k];
        float sp = (q > 20.f) ? q : __logf(1.f + __expf(q));
        dv[k+1] = 0.001f + sp;
    }
    float xin = fminf(fmaxf(x1v, -5.f), 5.f);
    int cnt = 0;
    #pragma unroll
    for (int k=0;k<10;k++) cnt += (xin >= cw[k]) ? 1 : 0;
    int bin = cnt-1; if (bin < 0) bin = 0; if (bin > 9) bin = 9;

    float icw=cw[bin], iw=wd[bin], ich=ch[bin], ih=hg[bin];
    float dl=dv[bin], dr=dv[bin+1];
    float riw = __fdividef(1.f, iw);
    float delta = ih*riw;
    float th  = (xin - icw)*riw;
    float t1m = th*(1.f-th);
    float num = ih*(delta*th*th + dl*t1m);
    float den = delta + (dl+dr-2.f*delta)*t1m;
    float yv  = ich + __fdividef(num, den);
    float onem = 1.f-th;
    float dnum = delta*delta*(dr*th*th + 2.f*delta*t1m + dl*onem*onem);
    float lad  = __logf(dnum) - 2.f*__logf(den);
    bool inside = (x1v >= -5.f) && (x1v <= 5.f);
    float xo   = inside ? yv  : x1v;
    float ladv = inside ? lad : 0.f;

    out[(size_t)b*2*TLEN + t]        = x0v * m;
    out[(size_t)b*2*TLEN + TLEN + t] = xo  * m;
    g_lad[pos] = ladv * m;
}

__global__ void logdet_kernel(float* __restrict__ out) {
    int b = blockIdx.x, tid = threadIdx.x;
    float s = 0.f;
    #pragma unroll
    for (int k=0;k<16;k++) s += g_lad[b*TLEN + k*256 + tid];
    __shared__ float smr[256];
    smr[tid] = s; __syncthreads();
    #pragma unroll
    for (int o=128;o;o>>=1){ if (tid<o) smr[tid]+=smr[tid+o]; __syncthreads(); }
    if (tid==0) out[b] = smr[0];
}

extern "C" void kernel_launch(void* const* d_in, const int* in_sizes, int n_in,
                              void* d_out, int out_size) {
    const float* x      = (const float*)d_in[0];
    const float* mask   = (const float*)d_in[1];
    const float* pre_w  = (const float*)d_in[2];
    const float* pre_b  = (const float*)d_in[3];
    const float* sep_w  = (const float*)d_in[4];
    const float* sep_b  = (const float*)d_in[5];
    const float* pw_w   = (const float*)d_in[6];
    const float* pw_b   = (const float*)d_in[7];
    const float* ln1_g  = (const float*)d_in[8];
    const float* ln1_b  = (const float*)d_in[9];
    const float* ln2_g  = (const float*)d_in[10];
    const float* ln2_b  = (const float*)d_in[11];
    const float* proj_w = (const float*)d_in[12];
    const float* proj_b = (const float*)d_in[13];
    float* out = (float*)d_out;

    float* hbuf[2];
    cudaGetSymbolAddress((void**)&hbuf[0], g_h0);
    cudaGetSymbolAddress((void**)&hbuf[1], g_h1);

    cudaFuncSetAttribute(fused_layer_mma,
                         cudaFuncAttributeMaxDynamicSharedMemorySize, SMEM_FL);

    // shifts the ncu profiling window so it captures fused_layer_mma
    prof_shift_kernel<<<1, 32>>>();

    int d = 1;
    for (int i = 0; i < 3; i++) {
        int first = (i == 0);
        int last  = (i == 2);
        const float* hin = hbuf[(i+1) & 1];
        float* hout      = hbuf[i & 1];
        fused_layer_mma<<<BT/64, 256, SMEM_FL>>>(
            hin, hout,
            pw_w + (size_t)i*C*C, pw_b + (size_t)i*C,
            ln2_g + (size_t)i*C, ln2_b + (size_t)i*C,
            sep_w + (size_t)i*C*3, sep_b + (size_t)i*C,
            ln1_g + (size_t)i*C, ln1_b + (size_t)i*C,
            mask, x, pre_w, pre_b,
            proj_w, proj_b, d, first, last);
        d *= 3;
    }

    spline_kernel<<<BT/256, 256>>>(x, mask, out);
    logdet_kernel<<<64, 256>>>(out + (size_t)BATCH*2*TLEN);
}